// round 1
// baseline (speedup 1.0000x reference)
#include <cuda_runtime.h>

// ---------------------------------------------------------------------------
// Gcs_loss: total = ( sum_i sqrt(S2x - 2*dot_x(i) + P*colsq_x(i))
//                   + sum_i sqrt(S2y - 2*dot_y(i) + P*colsq_y(i)) ) / (B*2)
// with v = pred - truth, split into X = v[:, :P], Y = v[:, P:].
//   B = 32, P = 1024.
// Expansion of sum_{b,j} (v[b,j] - v[b,i])^2:
//   = S2 - 2 * sum_b v[b,i]*rowsum[b] + P * sum_b v[b,i]^2
// ---------------------------------------------------------------------------

#define GB  32
#define GP  1024

__device__ float        g_partial[2];
__device__ unsigned int g_done;   // static-initialized to 0; reset each launch

__global__ void gcs_loss_kernel(const float* __restrict__ pred,
                                const float* __restrict__ truth,
                                float* __restrict__ out)
{
    extern __shared__ float sv[];          // v values: [GB][GP]  = 128 KB
    __shared__ float s_rowsum[GB];
    __shared__ float s_sumsq[GB];
    __shared__ float s_red[GB];

    const int half = blockIdx.x;           // 0 = X, 1 = Y
    const int tid  = threadIdx.x;          // 0..1023
    const int warp = tid >> 5;             // warp w handles row b = w
    const int lane = tid & 31;

    // ---------------- Phase 1: load v = pred - truth, rowsum & sumsq -------
    {
        const int row = warp;
        const float4* p4 = (const float4*)(pred  + row * (2 * GP) + half * GP);
        const float4* t4 = (const float4*)(truth + row * (2 * GP) + half * GP);
        float4* v4 = (float4*)(sv + row * GP);

        float rs = 0.f, sq = 0.f;
        #pragma unroll
        for (int k = 0; k < GP / 4 / 32; k++) {        // 8 iterations
            int idx = lane + 32 * k;                   // float4 index 0..255
            float4 p = p4[idx];
            float4 t = t4[idx];
            float4 v;
            v.x = p.x - t.x; v.y = p.y - t.y;
            v.z = p.z - t.z; v.w = p.w - t.w;
            v4[idx] = v;
            rs += (v.x + v.y) + (v.z + v.w);
            sq += v.x * v.x + v.y * v.y + v.z * v.z + v.w * v.w;
        }
        #pragma unroll
        for (int off = 16; off; off >>= 1) {
            rs += __shfl_xor_sync(0xffffffff, rs, off);
            sq += __shfl_xor_sync(0xffffffff, sq, off);
        }
        if (lane == 0) { s_rowsum[row] = rs; s_sumsq[row] = sq; }
    }
    __syncthreads();

    // ---------------- Phase 2: per-anchor distance --------------------------
    float S2 = 0.f;
    #pragma unroll
    for (int b = 0; b < GB; b++) S2 += s_sumsq[b];

    float dot = 0.f, colsq = 0.f;
    #pragma unroll
    for (int b = 0; b < GB; b++) {
        float v = sv[b * GP + tid];
        dot   += v * s_rowsum[b];
        colsq += v * v;
    }
    float s   = S2 - 2.0f * dot + (float)GP * colsq;
    float val = sqrtf(fmaxf(s, 0.0f));

    // ---------------- block reduction of sum of sqrts -----------------------
    #pragma unroll
    for (int off = 16; off; off >>= 1)
        val += __shfl_xor_sync(0xffffffff, val, off);
    if (lane == 0) s_red[warp] = val;
    __syncthreads();

    if (warp == 0) {
        float v = s_red[lane];
        #pragma unroll
        for (int off = 16; off; off >>= 1)
            v += __shfl_xor_sync(0xffffffff, v, off);

        if (lane == 0) {
            g_partial[half] = v;
            __threadfence();
            unsigned int prev = atomicAdd(&g_done, 1u);
            if (prev == 1) {               // I am the last block to finish
                __threadfence();
                float total = *(volatile float*)&g_partial[0]
                            + *(volatile float*)&g_partial[1];
                *out = total / (float)(GB * 2);
                g_done = 0;                // reset for next (graph) replay
            }
        }
    }
}

extern "C" void kernel_launch(void* const* d_in, const int* in_sizes, int n_in,
                              void* d_out, int out_size)
{
    (void)in_sizes; (void)n_in; (void)out_size;
    const float* pred  = (const float*)d_in[0];
    const float* truth = (const float*)d_in[1];
    float* out = (float*)d_out;

    const int smem = GB * GP * (int)sizeof(float);   // 128 KB
    cudaFuncSetAttribute(gcs_loss_kernel,
                         cudaFuncAttributeMaxDynamicSharedMemorySize, smem);
    gcs_loss_kernel<<<2, 1024, smem>>>(pred, truth, out);
}

// round 2
// speedup vs baseline: 1.0554x; 1.0554x over previous
#include <cuda_runtime.h>

// ---------------------------------------------------------------------------
// Gcs_loss, expanded form:
//   v = pred - truth, halves X = v[:,:P], Y = v[:,P:]
//   s_i = S2 - 2 * sum_b v[b,i]*rowsum[b] + P * sum_b v[b,i]^2
//   out = ( sum_i sqrt(s_i^X) + sum_i sqrt(s_i^Y) ) / (2B)
// B=32, P=1024.
//
// 16 blocks: bid>>3 = half, bid&7 = column slice (128 cols).
// Single launch with a spin grid-sync (16 blocks always co-resident).
// ---------------------------------------------------------------------------

#define GB      32
#define GP      1024
#define NBLK    16
#define SLICES  8
#define SCOLS   128          // columns per slice

__device__ float        g_prs[NBLK][GB];   // per-slice partial rowsums
__device__ float        g_psq[NBLK];       // per-slice partial sum of squares
__device__ float        g_bsum[NBLK];      // per-block sum of sqrts
__device__ unsigned int g_arrive;          // grid-sync counter (reset each launch)
__device__ unsigned int g_done;            // completion counter (reset each launch)

__global__ void __launch_bounds__(1024, 1)
gcs_loss_kernel(const float* __restrict__ pred,
                const float* __restrict__ truth,
                float* __restrict__ out)
{
    __shared__ float sv[GB * SCOLS];       // 16 KB: v slice [32 rows][128 cols]
    __shared__ float s_sq[GB];
    __shared__ float s_rowsum[GB];
    __shared__ float s_S2;
    __shared__ float s_red[4];

    const int bid   = blockIdx.x;
    const int half  = bid >> 3;
    const int slice = bid & 7;
    const int tid   = threadIdx.x;         // 0..1023
    const int row   = tid >> 5;            // warp w == row w
    const int lane  = tid & 31;

    // ---------------- Phase 1: load v slice, per-row partial sums ----------
    {
        const float* pbase = pred  + row * (2 * GP) + half * GP + slice * SCOLS;
        const float* tbase = truth + row * (2 * GP) + half * GP + slice * SCOLS;
        float4 p = ((const float4*)pbase)[lane];
        float4 t = ((const float4*)tbase)[lane];
        float4 v;
        v.x = p.x - t.x; v.y = p.y - t.y; v.z = p.z - t.z; v.w = p.w - t.w;
        ((float4*)(sv + row * SCOLS))[lane] = v;

        float rs = (v.x + v.y) + (v.z + v.w);
        float sq = v.x * v.x + v.y * v.y + v.z * v.z + v.w * v.w;
        #pragma unroll
        for (int off = 16; off; off >>= 1) {
            rs += __shfl_xor_sync(0xffffffff, rs, off);
            sq += __shfl_xor_sync(0xffffffff, sq, off);
        }
        if (lane == 0) {
            g_prs[bid][row] = rs;          // global partial rowsum
            s_sq[row] = sq;
            __threadfence();               // make g_prs visible chip-wide
        }
    }
    __syncthreads();

    // slice sum-of-squares -> global
    if (tid < 32) {
        float sq = s_sq[lane];
        #pragma unroll
        for (int off = 16; off; off >>= 1)
            sq += __shfl_xor_sync(0xffffffff, sq, off);
        if (lane == 0) {
            g_psq[bid] = sq;
            __threadfence();
            atomicAdd(&g_arrive, 1u);      // arrive at grid barrier
        }
    }

    // ---------------- grid sync (spin) --------------------------------------
    if (tid == 0) {
        while (*(volatile unsigned int*)&g_arrive < NBLK) { }
        __threadfence();                   // acquire
    }
    __syncthreads();

    // ---------------- Phase 2: combine partials, per-anchor ----------------
    if (tid < 32) {
        float rs = 0.f;
        #pragma unroll
        for (int s = 0; s < SLICES; s++)
            rs += g_prs[half * SLICES + s][lane];
        s_rowsum[lane] = rs;
        if (lane == 0) {
            float S2 = 0.f;
            #pragma unroll
            for (int s = 0; s < SLICES; s++)
                S2 += g_psq[half * SLICES + s];
            s_S2 = S2;
        }
    }
    __syncthreads();

    float val = 0.f;
    if (tid < SCOLS) {
        float dot = 0.f, colsq = 0.f;
        #pragma unroll
        for (int b = 0; b < GB; b++) {
            float v = sv[b * SCOLS + tid];
            dot   += v * s_rowsum[b];
            colsq += v * v;
        }
        float s = s_S2 - 2.0f * dot + (float)GP * colsq;
        val = sqrtf(fmaxf(s, 0.0f));
    }

    // reduce 128 values (4 warps have nonzero)
    if (tid < SCOLS) {
        #pragma unroll
        for (int off = 16; off; off >>= 1)
            val += __shfl_xor_sync(0xffffffff, val, off);
        if (lane == 0) s_red[tid >> 5] = val;
    }
    __syncthreads();

    if (tid == 0) {
        float bs = s_red[0] + s_red[1] + s_red[2] + s_red[3];
        g_bsum[bid] = bs;
        __threadfence();
        unsigned int prev = atomicAdd(&g_done, 1u);
        if (prev == NBLK - 1) {            // last block: final combine
            __threadfence();
            float total = 0.f;
            #pragma unroll
            for (int i = 0; i < NBLK; i++)
                total += *(volatile float*)&g_bsum[i];
            *out = total / (float)(GB * 2);
            g_arrive = 0;                  // reset for next launch/replay
            g_done   = 0;
        }
    }
}

extern "C" void kernel_launch(void* const* d_in, const int* in_sizes, int n_in,
                              void* d_out, int out_size)
{
    (void)in_sizes; (void)n_in; (void)out_size;
    const float* pred  = (const float*)d_in[0];
    const float* truth = (const float*)d_in[1];
    float* out = (float*)d_out;

    gcs_loss_kernel<<<NBLK, 1024>>>(pred, truth, out);
}

// round 3
// speedup vs baseline: 1.2657x; 1.1993x over previous
#include <cuda_runtime.h>
#include <cooperative_groups.h>

namespace cg = cooperative_groups;

// ---------------------------------------------------------------------------
// Gcs_loss, expanded form:
//   v = pred - truth, halves X = v[:,:P], Y = v[:,P:]
//   s_i = S2 - 2 * sum_b v[b,i]*rowsum[b] + P * sum_b v[b,i]^2
//   out = ( sum_i sqrt(s_i^X) + sum_i sqrt(s_i^Y) ) / (2B)
// B=32, P=1024.
//
// Grid = 16 CTAs = 2 clusters of 8 (cluster == one half).
// Intra-half reduction via cluster.sync + DSMEM (no global fences/spins).
// Cross-half combine via one release-atomic + acquire loads.
// ---------------------------------------------------------------------------

#define GB      32
#define GP      1024
#define SCOLS   128          // columns per slice (8 slices per half)

__device__ float        g_bs[2];   // per-half sum of sqrts (plain stores, idempotent)
__device__ unsigned int g_done;    // cross-half completion counter (reset each launch)

__device__ __forceinline__ unsigned atom_add_release_gpu(unsigned int* p, unsigned v)
{
    unsigned old;
    asm volatile("atom.release.gpu.global.add.u32 %0, [%1], %2;"
                 : "=r"(old) : "l"(p), "r"(v) : "memory");
    return old;
}

__device__ __forceinline__ float ld_acquire_gpu_f32(const float* p)
{
    float v;
    asm volatile("ld.acquire.gpu.global.f32 %0, [%1];"
                 : "=f"(v) : "l"(p) : "memory");
    return v;
}

__global__ void __launch_bounds__(1024, 1) __cluster_dims__(8, 1, 1)
gcs_loss_kernel(const float* __restrict__ pred,
                const float* __restrict__ truth,
                float* __restrict__ out)
{
    __shared__ float sv[GB * SCOLS];   // 16 KB: v slice [32 rows][128 cols]
    __shared__ float s_part[GB];       // this slice's per-row partial rowsums (DSMEM-read by peers)
    __shared__ float s_sqpart;         // this slice's sum of squares        (DSMEM-read by peers)
    __shared__ float s_bs;             // this block's sum of sqrts          (DSMEM-read by rank0)
    __shared__ float s_sq[GB];
    __shared__ float s_rowsum[GB];
    __shared__ float s_S2;
    __shared__ float s_red[4];

    cg::cluster_group cluster = cg::this_cluster();

    const int bid   = blockIdx.x;
    const int half  = bid >> 3;        // 0 = X, 1 = Y  (cluster id)
    const int slice = bid & 7;         // rank within cluster
    const int tid   = threadIdx.x;     // 0..1023
    const int row   = tid >> 5;        // warp w == row w
    const int lane  = tid & 31;

    // ---------------- Phase 1: load v slice, per-row partial sums ----------
    {
        const float* pb = pred  + row * (2 * GP) + half * GP + slice * SCOLS;
        const float* tb = truth + row * (2 * GP) + half * GP + slice * SCOLS;
        float4 p = ((const float4*)pb)[lane];
        float4 t = ((const float4*)tb)[lane];
        float4 v;
        v.x = p.x - t.x; v.y = p.y - t.y; v.z = p.z - t.z; v.w = p.w - t.w;
        ((float4*)(sv + row * SCOLS))[lane] = v;

        float rs = (v.x + v.y) + (v.z + v.w);
        float sq = v.x * v.x + v.y * v.y + v.z * v.z + v.w * v.w;
        #pragma unroll
        for (int off = 16; off; off >>= 1) {
            rs += __shfl_xor_sync(0xffffffff, rs, off);
            sq += __shfl_xor_sync(0xffffffff, sq, off);
        }
        if (lane == 0) { s_part[row] = rs; s_sq[row] = sq; }
    }
    __syncthreads();

    if (tid < 32) {
        float q = s_sq[lane];
        #pragma unroll
        for (int off = 16; off; off >>= 1)
            q += __shfl_xor_sync(0xffffffff, q, off);
        if (lane == 0) s_sqpart = q;
    }

    // ---------------- cluster barrier #1: partials published ----------------
    cluster.sync();

    // ---------------- gather peers' partials via DSMEM (warp 0) ------------
    if (tid < 32) {
        float rtot = 0.f;
        #pragma unroll
        for (int r = 0; r < 8; r++) {
            const float* prem =
                (const float*)cluster.map_shared_rank((void*)s_part, r);
            rtot += prem[lane];
        }
        s_rowsum[lane] = rtot;

        float q = 0.f;
        if (lane < 8) {
            const float* qrem =
                (const float*)cluster.map_shared_rank((void*)&s_sqpart, lane);
            q = *qrem;
        }
        #pragma unroll
        for (int off = 4; off; off >>= 1)
            q += __shfl_xor_sync(0xffffffff, q, off);
        if (lane == 0) s_S2 = q;
    }
    __syncthreads();

    // ---------------- Phase 2: per-anchor distance (128 anchors/block) -----
    if (tid < SCOLS) {
        float dot = 0.f, colsq = 0.f;
        #pragma unroll
        for (int b = 0; b < GB; b++) {
            float v = sv[b * SCOLS + tid];
            dot   += v * s_rowsum[b];
            colsq += v * v;
        }
        float s   = s_S2 - 2.0f * dot + (float)GP * colsq;
        float val = sqrtf(fmaxf(s, 0.0f));
        #pragma unroll
        for (int off = 16; off; off >>= 1)
            val += __shfl_xor_sync(0xffffffff, val, off);
        if (lane == 0) s_red[tid >> 5] = val;
    }
    __syncthreads();
    if (tid == 0)
        s_bs = s_red[0] + s_red[1] + s_red[2] + s_red[3];

    // ---------------- cluster barrier #2: block sums published --------------
    cluster.sync();

    // rank 0 of each cluster gathers its half's 8 block sums
    if (slice == 0 && tid == 0) {
        float hs = 0.f;
        #pragma unroll
        for (int r = 0; r < 8; r++) {
            const float* brem =
                (const float*)cluster.map_shared_rank((void*)&s_bs, r);
            hs += *brem;
        }
        g_bs[half] = hs;                       // plain store, idempotent
        unsigned prev = atom_add_release_gpu(&g_done, 1u);
        if (prev == 1) {                       // last half: final combine
            float a = ld_acquire_gpu_f32(&g_bs[0]);
            float c = ld_acquire_gpu_f32(&g_bs[1]);
            *out = (a + c) * (1.0f / (float)(GB * 2));
            g_done = 0;                        // reset for next replay
        }
    }

    // ---------------- cluster barrier #3: keep smem alive for rank0 --------
    cluster.sync();
}

extern "C" void kernel_launch(void* const* d_in, const int* in_sizes, int n_in,
                              void* d_out, int out_size)
{
    (void)in_sizes; (void)n_in; (void)out_size;
    const float* pred  = (const float*)d_in[0];
    const float* truth = (const float*)d_in[1];
    float* out = (float*)d_out;

    gcs_loss_kernel<<<16, 1024>>>(pred, truth, out);
}